// round 4
// baseline (speedup 1.0000x reference)
#include <cuda_runtime.h>
#include <cuda_bf16.h>
#include <cstdint>

// Problem constants
#define Bb 2
#define Cc 256
#define Hh 128
#define Ww 128
#define Oo 256
#define HW 16384            // H*W
#define DG 4
#define GC 64               // channels per deform group
#define OFFC 72             // DG*9*2 offset channels
#define NGT 36              // DG * 9 taps; K-chunk = 64 channels

#define SSTR 68             // padded smem row stride for S (floats)
#define WBYTES 65536        // one W buffer: 256o x 64c x 4B (swizzled, no pad)

// Scratch (device globals: allocation-free rule)
__device__ float g_off[Bb * OFFC * HW];       // offset field [b][72][h][w]
__device__ float g_wt[NGT * Oo * GC];         // weights tf32, [chunk], pre-swizzled 256x64 tile

// ---------------------------------------------------------------------------
// helpers
// ---------------------------------------------------------------------------
__device__ __forceinline__ uint32_t smem_u32(const void* p) {
    uint32_t a;
    asm("{ .reg .u64 t; cvta.to.shared.u64 t, %1; cvt.u32.u64 %0, t; }" : "=r"(a) : "l"(p));
    return a;
}
__device__ __forceinline__ float to_tf32(float f) {
    uint32_t u;
    asm("cvt.rna.tf32.f32 %0, %1;" : "=r"(u) : "f"(f));
    return __uint_as_float(u);
}
__device__ __forceinline__ void ldsm4(uint32_t* r, uint32_t addr) {
    asm volatile("ldmatrix.sync.aligned.m8n8.x4.shared.b16 {%0,%1,%2,%3}, [%4];"
                 : "=r"(r[0]), "=r"(r[1]), "=r"(r[2]), "=r"(r[3]) : "r"(addr));
}
__device__ __forceinline__ void mma_tf32(float* c, const uint32_t* a, const uint32_t* b) {
    asm volatile(
        "mma.sync.aligned.m16n8k8.row.col.f32.tf32.tf32.f32 "
        "{%0,%1,%2,%3},{%4,%5,%6,%7},{%8,%9},{%0,%1,%2,%3};"
        : "+f"(c[0]), "+f"(c[1]), "+f"(c[2]), "+f"(c[3])
        : "r"(a[0]), "r"(a[1]), "r"(a[2]), "r"(a[3]), "r"(b[0]), "r"(b[1]));
}
__device__ __forceinline__ void sts128(uint32_t a, float x, float y, float z, float w) {
    asm volatile("st.shared.v4.f32 [%0], {%1,%2,%3,%4};" :: "r"(a), "f"(x), "f"(y), "f"(z), "f"(w));
}
__device__ __forceinline__ void cp16(uint32_t dst, const void* src) {
    asm volatile("cp.async.cg.shared.global [%0], [%1], 16;" :: "r"(dst), "l"(src) : "memory");
}
__device__ __forceinline__ void cp_commit() {
    asm volatile("cp.async.commit_group;" ::: "memory");
}
template <int N>
__device__ __forceinline__ void cp_wait() {
    asm volatile("cp.async.wait_group %0;" :: "n"(N) : "memory");
}

// ---------------------------------------------------------------------------
// K0: transpose + tf32-round + XOR-swizzle deform weights
// [O][C][3][3] -> g_wt[chunk=g*9+tap][ f4idx = o*16 + ((c>>2)^(o&7)) ][c&3]
// (so cp.async staging into smem is a straight contiguous copy; ldmatrix rows
//  of 256B stride become conflict-free via the XOR on 16B columns)
// ---------------------------------------------------------------------------
__global__ void k_transpose_w(const float* __restrict__ w) {
    int idx = blockIdx.x * blockDim.x + threadIdx.x;
    if (idx >= Oo * Cc * 9) return;
    int o = idx / (Cc * 9);
    int r = idx % (Cc * 9);
    int c = r / 9;
    int tap = r % 9;
    int g = c >> 6;
    int cc = c & 63;
    int f4 = o * 16 + ((cc >> 2) ^ (o & 7));
    g_wt[(size_t)(g * 9 + tap) * (Oo * GC) + f4 * 4 + (cc & 3)] = to_tf32(w[idx]);
}

// ---------------------------------------------------------------------------
// K1: offset field = 1x1 conv (72x256 matvec per pixel) + bias
// ---------------------------------------------------------------------------
__global__ __launch_bounds__(128) void k_offset(const float* __restrict__ x,
                                                const float* __restrict__ w_off,
                                                const float* __restrict__ b_off) {
    extern __shared__ float ws[];  // [256][72], c-major
    for (int i = threadIdx.x; i < OFFC * Cc; i += blockDim.x) {
        int o = i / Cc, c = i % Cc;
        ws[c * OFFC + o] = w_off[i];
    }
    __syncthreads();

    int pix = blockIdx.x * 128 + threadIdx.x;
    int b = pix >> 14;
    int hw = pix & (HW - 1);
    const float* xp = x + (size_t)b * Cc * HW + hw;

    float4 acc[18];
#pragma unroll
    for (int i = 0; i < 18; i++) acc[i] = *(const float4*)&b_off[i * 4];

    for (int c = 0; c < Cc; c++) {
        float v = __ldg(&xp[(size_t)c * HW]);
        const float4* wrow = (const float4*)&ws[c * OFFC];
#pragma unroll
        for (int i = 0; i < 18; i++) {
            float4 w4 = wrow[i];
            acc[i].x = fmaf(v, w4.x, acc[i].x);
            acc[i].y = fmaf(v, w4.y, acc[i].y);
            acc[i].z = fmaf(v, w4.z, acc[i].z);
            acc[i].w = fmaf(v, w4.w, acc[i].w);
        }
    }
    float* op = g_off + (size_t)b * OFFC * HW + hw;
#pragma unroll
    for (int i = 0; i < 18; i++) {
        op[(i * 4 + 0) * HW] = acc[i].x;
        op[(i * 4 + 1) * HW] = acc[i].y;
        op[(i * 4 + 2) * HW] = acc[i].z;
        op[(i * 4 + 3) * HW] = acc[i].w;
    }
}

// ---------------------------------------------------------------------------
// K2: fused deformable conv + ReLU, tf32 mma.sync m16n8k8.
// CTA = (b, row h): 128 pixels x 256 outputs. 36 K-chunks of 64c.
// W double-buffered via cp.async (pre-swizzled, contiguous copy), S padded.
// 8 warps in 2(p-half) x 4(o-quarter): each warp 64p x 64o (4 mi x 8 ni).
// ---------------------------------------------------------------------------
__global__ __launch_bounds__(256, 1) void k_deform(const float* __restrict__ x,
                                                   float* __restrict__ out) {
    extern __shared__ float dsm[];
    // layout: W buf0 [0,64K), W buf1 [64K,128K), S [128K, 128K+34816)
    float* sS = dsm + 2 * (WBYTES / 4);

    const int bx = blockIdx.x;
    const int h = bx & 127;
    const int b = bx >> 7;
    const int tid = threadIdx.x;
    const int wid = tid >> 5;
    const int lid = tid & 31;
    const int wp = wid >> 2;       // p-half (64p)
    const int wo = wid & 3;        // o-quarter (64o)

    const uint32_t sWb[2] = {smem_u32(dsm), smem_u32(dsm) + WBYTES};
    const uint32_t sSb = smem_u32(sS);

    // ldmatrix lane addressing (R3-validated recipe)
    const uint32_t a_row8 = (lid & 7) + ((lid >> 3) & 1) * 8;   // 0..15
    const uint32_t a_col = (lid >> 4) * 4;                      // 0 or 4
    const uint32_t aBase = sSb + ((wp * 64 + a_row8) * SSTR + a_col) * 4;
    const uint32_t b_row8 = (lid & 7) + ((lid >> 4) & 1) * 8;   // 0..15
    const uint32_t b_csel = (lid >> 3) & 1;                     // 0 or 1 (16B col)
    const uint32_t b_sw = b_row8 & 7;

    float acc[4][8][4];
#pragma unroll
    for (int i = 0; i < 4; i++)
#pragma unroll
        for (int j = 0; j < 8; j++)
#pragma unroll
            for (int k = 0; k < 4; k++) acc[i][j][k] = 0.f;

    const int sp = tid & 127;      // this thread's pixel (column in row h)
    const int chalf = tid >> 7;    // 0/1: which 32 channels of the 64-chunk

    // prefetch W chunk 0 into buf0 (16 f4 per thread)
    {
        const float4* wsrc = (const float4*)g_wt;
#pragma unroll
        for (int it = 0; it < 16; ++it) {
            int i = tid + it * 256;
            cp16(sWb[0] + (uint32_t)i * 16u, wsrc + i);
        }
        cp_commit();
    }

    for (int gt = 0; gt < NGT; ++gt) {
        const int g = gt / 9;
        const int tap = gt - g * 9;
        const int buf = gt & 1;

        // --- bilinear sample 32 channels for pixel sp into registers ---
        float v[32];
        {
            const float* offp = g_off + ((size_t)(b * OFFC + g * 18 + tap * 2)) * HW + h * Ww + sp;
            float dy = __ldg(offp);
            float dx = __ldg(offp + HW);
            float ys = (float)(h - 1 + tap / 3) + dy;
            float xs = (float)(sp - 1 + tap % 3) + dx;
            float y0f = floorf(ys), x0f = floorf(xs);
            float ly = ys - y0f, lx = xs - x0f;
            int y0 = (int)y0f, x0i = (int)x0f;
            float wt[4];
            const float* qp[4];
            const float* xb = x + ((size_t)(b * Cc + g * GC + chalf * 32)) * HW;
#pragma unroll
            for (int j = 0; j < 4; ++j) {
                int yj = y0 + (j >> 1);
                int xj = x0i + (j & 1);
                float wj = ((j >> 1) ? ly : 1.f - ly) * ((j & 1) ? lx : 1.f - lx);
                bool vv = (yj >= 0) && (yj < Hh) && (xj >= 0) && (xj < Ww);
                int yc = min(max(yj, 0), Hh - 1);
                int xc = min(max(xj, 0), Ww - 1);
                wt[j] = vv ? wj : 0.f;
                qp[j] = xb + (yc * Ww + xc);
            }
#pragma unroll 8
            for (int c = 0; c < 32; ++c) {
                v[c] = to_tf32(wt[0] * __ldg(qp[0] + (size_t)c * HW) +
                               wt[1] * __ldg(qp[1] + (size_t)c * HW) +
                               wt[2] * __ldg(qp[2] + (size_t)c * HW) +
                               wt[3] * __ldg(qp[3] + (size_t)c * HW));
            }
        }

        // --- prefetch next W chunk (other buffer is safe: its last reader
        //     was GEMM(gt-1), which finished before the trailing sync) ---
        if (gt + 1 < NGT) {
            const float4* wsrc = (const float4*)(g_wt + (size_t)(gt + 1) * (Oo * GC));
#pragma unroll
            for (int it = 0; it < 16; ++it) {
                int i = tid + it * 256;
                cp16(sWb[(gt + 1) & 1] + (uint32_t)i * 16u, wsrc + i);
            }
            cp_commit();
            cp_wait<1>();     // current chunk's W has landed
        } else {
            cp_wait<0>();
        }

        __syncthreads();      // prev GEMM done reading S

        // --- store sampled values to S [128p][68] ---
#pragma unroll
        for (int j4 = 0; j4 < 8; ++j4) {
            sts128(sSb + (uint32_t)(sp * SSTR + chalf * 32 + j4 * 4) * 4u,
                   v[j4 * 4 + 0], v[j4 * 4 + 1], v[j4 * 4 + 2], v[j4 * 4 + 3]);
        }
        __syncthreads();      // S + W visible to all

        // --- GEMM: acc[64p x 64o per warp] += S * W^T over 64 c ---
#pragma unroll
        for (int ks = 0; ks < 8; ++ks) {
            uint32_t afr[4][4];
#pragma unroll
            for (int mi = 0; mi < 4; ++mi)
                ldsm4(afr[mi], aBase + (uint32_t)(mi * 16 * SSTR + ks * 8) * 4u);
            uint32_t bfr[4][4];
#pragma unroll
            for (int pi = 0; pi < 4; ++pi) {
                uint32_t row = wo * 64 + pi * 16 + b_row8;
                uint32_t colf4 = ((uint32_t)(ks * 2) + b_csel) ^ b_sw;
                ldsm4(bfr[pi], sWb[buf] + row * 256u + colf4 * 16u);
            }
#pragma unroll
            for (int mi = 0; mi < 4; ++mi)
#pragma unroll
                for (int ni = 0; ni < 8; ++ni)
                    mma_tf32(acc[mi][ni], afr[mi], &bfr[ni >> 1][(ni & 1) * 2]);
        }
        __syncthreads();      // GEMM done before next S write / W overwrite
    }

    // --- epilogue: ReLU + store ---
    {
        const int gq = lid >> 2;   // 0..7
        const int tq = lid & 3;    // 0..3
#pragma unroll
        for (int mi = 0; mi < 4; ++mi) {
#pragma unroll
            for (int ni = 0; ni < 8; ++ni) {
                int o = wo * 64 + ni * 8 + 2 * tq;
                int p = wp * 64 + mi * 16 + gq;
                float* op = out + ((size_t)(b * Oo + o)) * HW + h * Ww + p;
                op[0] = fmaxf(acc[mi][ni][0], 0.f);
                op[HW] = fmaxf(acc[mi][ni][1], 0.f);
                op[8] = fmaxf(acc[mi][ni][2], 0.f);
                op[HW + 8] = fmaxf(acc[mi][ni][3], 0.f);
            }
        }
    }
}

// ---------------------------------------------------------------------------
extern "C" void kernel_launch(void* const* d_in, const int* in_sizes, int n_in,
                              void* d_out, int out_size) {
    const float* x = (const float*)d_in[0];        // [2,256,128,128]
    const float* w_off = (const float*)d_in[1];    // [72,256,1,1]
    const float* b_off = (const float*)d_in[2];    // [72]
    const float* w_def = (const float*)d_in[3];    // [256,256,3,3]
    float* out = (float*)d_out;

    const int OFF_SMEM = OFFC * Cc * sizeof(float);          // 73728
    const int DEF_SMEM = 2 * WBYTES + 128 * SSTR * 4;        // 165888

    cudaFuncSetAttribute(k_offset, cudaFuncAttributeMaxDynamicSharedMemorySize, OFF_SMEM);
    cudaFuncSetAttribute(k_deform, cudaFuncAttributeMaxDynamicSharedMemorySize, DEF_SMEM);

    k_transpose_w<<<(Oo * Cc * 9 + 255) / 256, 256>>>(w_def);
    k_offset<<<(Bb * HW) / 128, 128, OFF_SMEM>>>(x, w_off, b_off);
    k_deform<<<Bb * Hh, 256, DEF_SMEM>>>(x, out);
}

// round 5
// speedup vs baseline: 1.1977x; 1.1977x over previous
#include <cuda_runtime.h>
#include <cuda_bf16.h>
#include <cstdint>

// Problem constants
#define Bb 2
#define Cc 256
#define Hh 128
#define Ww 128
#define Oo 256
#define HW 16384            // H*W
#define DG 4
#define OFFC 72             // DG*9*2 offset channels
#define NCH 72              // chunks: (g*2+chalf)*9 + tap, K=32 each
#define KC 32               // K per chunk
#define WB 32768            // W chunk bytes: 256o x 32c x 4B

// Scratch (device globals: allocation-free rule)
__device__ float g_off[Bb * OFFC * HW];        // offset field [b][72][h][w]
__device__ float g_wt[NCH * Oo * KC];          // weights tf32, [chunk], pre-swizzled 256x32 tile

// ---------------------------------------------------------------------------
// helpers
// ---------------------------------------------------------------------------
__device__ __forceinline__ uint32_t smem_u32(const void* p) {
    uint32_t a;
    asm("{ .reg .u64 t; cvta.to.shared.u64 t, %1; cvt.u32.u64 %0, t; }" : "=r"(a) : "l"(p));
    return a;
}
__device__ __forceinline__ float to_tf32(float f) {
    uint32_t u;
    asm("cvt.rna.tf32.f32 %0, %1;" : "=r"(u) : "f"(f));
    return __uint_as_float(u);
}
__device__ __forceinline__ void ldsm4(uint32_t* r, uint32_t addr) {
    asm volatile("ldmatrix.sync.aligned.m8n8.x4.shared.b16 {%0,%1,%2,%3}, [%4];"
                 : "=r"(r[0]), "=r"(r[1]), "=r"(r[2]), "=r"(r[3]) : "r"(addr));
}
__device__ __forceinline__ void mma_tf32(float* c, const uint32_t* a, const uint32_t* b) {
    asm volatile(
        "mma.sync.aligned.m16n8k8.row.col.f32.tf32.tf32.f32 "
        "{%0,%1,%2,%3},{%4,%5,%6,%7},{%8,%9},{%0,%1,%2,%3};"
        : "+f"(c[0]), "+f"(c[1]), "+f"(c[2]), "+f"(c[3])
        : "r"(a[0]), "r"(a[1]), "r"(a[2]), "r"(a[3]), "r"(b[0]), "r"(b[1]));
}
__device__ __forceinline__ void sts128(uint32_t a, float x, float y, float z, float w) {
    asm volatile("st.shared.v4.f32 [%0], {%1,%2,%3,%4};" :: "r"(a), "f"(x), "f"(y), "f"(z), "f"(w));
}
__device__ __forceinline__ void cp16(uint32_t dst, const void* src) {
    asm volatile("cp.async.cg.shared.global [%0], [%1], 16;" :: "r"(dst), "l"(src) : "memory");
}
__device__ __forceinline__ void cp_commit() {
    asm volatile("cp.async.commit_group;" ::: "memory");
}
template <int N>
__device__ __forceinline__ void cp_wait() {
    asm volatile("cp.async.wait_group %0;" :: "n"(N) : "memory");
}

// ---------------------------------------------------------------------------
// K0: transpose + tf32-round + XOR-swizzle deform weights.
// [O][C][3][3] -> g_wt[cid=(g*2+chalf)*9+tap][ f4 = o*8 + ((cc>>2)^(o&7)) ][cc&3]
// Rows are 32c = 128B (8 f4); XOR keeps ldmatrix reads conflict-free while
// cp.async staging stays a straight contiguous copy.
// ---------------------------------------------------------------------------
__global__ void k_transpose_w(const float* __restrict__ w) {
    int idx = blockIdx.x * blockDim.x + threadIdx.x;
    if (idx >= Oo * Cc * 9) return;
    int o = idx / (Cc * 9);
    int r = idx % (Cc * 9);
    int c = r / 9;
    int tap = r % 9;
    int g = c >> 6;
    int chalf = (c >> 5) & 1;
    int cc = c & 31;
    int cid = (g * 2 + chalf) * 9 + tap;
    int f4 = o * 8 + ((cc >> 2) ^ (o & 7));
    g_wt[(size_t)cid * (Oo * KC) + f4 * 4 + (cc & 3)] = to_tf32(w[idx]);
}

// ---------------------------------------------------------------------------
// K1: offset field = 1x1 conv (72x256 matvec per pixel) + bias
// ---------------------------------------------------------------------------
__global__ __launch_bounds__(128) void k_offset(const float* __restrict__ x,
                                                const float* __restrict__ w_off,
                                                const float* __restrict__ b_off) {
    extern __shared__ float ws[];  // [256][72], c-major
    for (int i = threadIdx.x; i < OFFC * Cc; i += blockDim.x) {
        int o = i / Cc, c = i % Cc;
        ws[c * OFFC + o] = w_off[i];
    }
    __syncthreads();

    int pix = blockIdx.x * 128 + threadIdx.x;
    int b = pix >> 14;
    int hw = pix & (HW - 1);
    const float* xp = x + (size_t)b * Cc * HW + hw;

    float4 acc[18];
#pragma unroll
    for (int i = 0; i < 18; i++) acc[i] = *(const float4*)&b_off[i * 4];

    for (int c = 0; c < Cc; c++) {
        float v = __ldg(&xp[(size_t)c * HW]);
        const float4* wrow = (const float4*)&ws[c * OFFC];
#pragma unroll
        for (int i = 0; i < 18; i++) {
            float4 w4 = wrow[i];
            acc[i].x = fmaf(v, w4.x, acc[i].x);
            acc[i].y = fmaf(v, w4.y, acc[i].y);
            acc[i].z = fmaf(v, w4.z, acc[i].z);
            acc[i].w = fmaf(v, w4.w, acc[i].w);
        }
    }
    float* op = g_off + (size_t)b * OFFC * HW + hw;
#pragma unroll
    for (int i = 0; i < 18; i++) {
        op[(i * 4 + 0) * HW] = acc[i].x;
        op[(i * 4 + 1) * HW] = acc[i].y;
        op[(i * 4 + 2) * HW] = acc[i].z;
        op[(i * 4 + 3) * HW] = acc[i].w;
    }
}

// ---------------------------------------------------------------------------
// K2: fused deformable conv + ReLU, tf32 mma.sync m16n8k8.
// CTA = (b, row h): 128 pixels x 256 outputs. 72 K-chunks of 32c, ordered
// (g, chalf) outer x tap inner so the gather window (~80KB) stays L1-resident
// across the 9 taps. W streamed with cp.async.cg (L1-bypass), double-buffered.
// 16 warps = 4(p-quarter, 32p) x 4(o-quarter, 64o); acc = 64 regs/thread.
// smem: W 2x32KB + S 16KB (both XOR-swizzled 128B rows) = 80KB.
// ---------------------------------------------------------------------------
__global__ __launch_bounds__(512, 1) void k_deform(const float* __restrict__ x,
                                                   float* __restrict__ out) {
    extern __shared__ float dsm[];
    const uint32_t sWb[2] = {smem_u32(dsm), smem_u32(dsm) + WB};
    const uint32_t sSb = smem_u32(dsm) + 2 * WB;

    const int bx = blockIdx.x;
    const int h = bx & 127;
    const int b = bx >> 7;
    const int tid = threadIdx.x;
    const int wid = tid >> 5;
    const int lid = tid & 31;
    const int wp = wid >> 2;       // p-quarter (32p)
    const int wo = wid & 3;        // o-quarter (64o)

    // ldmatrix lane addressing
    const uint32_t a_row16 = lid & 15;
    const uint32_t a_csel = lid >> 4;                 // 0/1 (16B col within k8)
    const uint32_t b_row8 = (lid & 7) + ((lid >> 4) & 1) * 8;
    const uint32_t b_csel = (lid >> 3) & 1;

    float acc[2][8][4];
#pragma unroll
    for (int i = 0; i < 2; i++)
#pragma unroll
        for (int j = 0; j < 8; j++)
#pragma unroll
            for (int k = 0; k < 4; k++) acc[i][j][k] = 0.f;

    const int sp = tid & 127;      // this thread's pixel
    const int cq = tid >> 7;       // 0..3: which 8 channels of the 32-chunk

    // prefetch W chunk 0 (4 f4 per thread)
    {
        const float4* wsrc = (const float4*)g_wt;
#pragma unroll
        for (int it = 0; it < 4; ++it) {
            int i = tid + it * 512;
            cp16(sWb[0] + (uint32_t)i * 16u, wsrc + i);
        }
        cp_commit();
    }

    for (int cid = 0; cid < NCH; ++cid) {
        const int gc = cid / 9;          // g*2+chalf
        const int tap = cid - gc * 9;
        const int g = gc >> 1;
        const int buf = cid & 1;

        // --- bilinear sample 8 channels for pixel sp ---
        float v[8];
        {
            const float* offp = g_off + ((size_t)(b * OFFC + g * 18 + tap * 2)) * HW + h * Ww + sp;
            float dy = __ldg(offp);
            float dx = __ldg(offp + HW);
            float ys = (float)(h - 1 + tap / 3) + dy;
            float xs = (float)(sp - 1 + tap % 3) + dx;
            float y0f = floorf(ys), x0f = floorf(xs);
            float ly = ys - y0f, lx = xs - x0f;
            int y0 = (int)y0f, x0i = (int)x0f;
            float wt[4];
            const float* qp[4];
            const float* xb = x + ((size_t)(b * Cc + gc * 32 + cq * 8)) * HW;
#pragma unroll
            for (int j = 0; j < 4; ++j) {
                int yj = y0 + (j >> 1);
                int xj = x0i + (j & 1);
                float wj = ((j >> 1) ? ly : 1.f - ly) * ((j & 1) ? lx : 1.f - lx);
                bool vv = (yj >= 0) && (yj < Hh) && (xj >= 0) && (xj < Ww);
                int yc = min(max(yj, 0), Hh - 1);
                int xc = min(max(xj, 0), Ww - 1);
                wt[j] = vv ? wj : 0.f;
                qp[j] = xb + (yc * Ww + xc);
            }
#pragma unroll
            for (int c = 0; c < 8; ++c) {
                v[c] = to_tf32(wt[0] * __ldg(qp[0] + (size_t)c * HW) +
                               wt[1] * __ldg(qp[1] + (size_t)c * HW) +
                               wt[2] * __ldg(qp[2] + (size_t)c * HW) +
                               wt[3] * __ldg(qp[3] + (size_t)c * HW));
            }
        }

        __syncthreads();   // GEMM(cid-1) done reading S and W buf (cid+1)&1

        // --- store S [128p][32c], XOR-swizzled 128B rows ---
#pragma unroll
        for (int j = 0; j < 2; ++j) {
            uint32_t f4 = (uint32_t)((cq * 2 + j) ^ (sp & 7));
            sts128(sSb + (uint32_t)sp * 128u + f4 * 16u,
                   v[j * 4 + 0], v[j * 4 + 1], v[j * 4 + 2], v[j * 4 + 3]);
        }

        // --- prefetch next W chunk into the buffer GEMM(cid-1) just released ---
        if (cid + 1 < NCH) {
            const float4* wsrc = (const float4*)(g_wt + (size_t)(cid + 1) * (Oo * KC));
#pragma unroll
            for (int it = 0; it < 4; ++it) {
                int i = tid + it * 512;
                cp16(sWb[(cid + 1) & 1] + (uint32_t)i * 16u, wsrc + i);
            }
            cp_commit();
            cp_wait<1>();     // W(cid) has landed
        } else {
            cp_wait<0>();
        }
        __syncthreads();      // S + W(cid) visible

        // --- GEMM: acc[32p x 64o per warp] += S * W^T over 32 c ---
#pragma unroll
        for (int ks = 0; ks < 4; ++ks) {
            uint32_t afr[2][4];
#pragma unroll
            for (int mi = 0; mi < 2; ++mi) {
                uint32_t row = (uint32_t)(wp * 32 + mi * 16) + a_row16;
                uint32_t f4 = ((uint32_t)(ks * 2) + a_csel) ^ (row & 7);
                ldsm4(afr[mi], sSb + row * 128u + f4 * 16u);
            }
            uint32_t bfr[4][4];
#pragma unroll
            for (int pi = 0; pi < 4; ++pi) {
                uint32_t row = (uint32_t)(wo * 64 + pi * 16) + b_row8;
                uint32_t f4 = ((uint32_t)(ks * 2) + b_csel) ^ (row & 7);
                ldsm4(bfr[pi], sWb[buf] + row * 128u + f4 * 16u);
            }
#pragma unroll
            for (int mi = 0; mi < 2; ++mi)
#pragma unroll
                for (int ni = 0; ni < 8; ++ni)
                    mma_tf32(acc[mi][ni], afr[mi], &bfr[ni >> 1][(ni & 1) * 2]);
        }
    }

    // --- epilogue: ReLU + store ---
    {
        const int gq = lid >> 2;   // 0..7
        const int tq = lid & 3;    // 0..3
#pragma unroll
        for (int mi = 0; mi < 2; ++mi) {
#pragma unroll
            for (int ni = 0; ni < 8; ++ni) {
                int o = wo * 64 + ni * 8 + 2 * tq;
                int p = wp * 32 + mi * 16 + gq;
                float* op = out + ((size_t)(b * Oo + o)) * HW + h * Ww + p;
                op[0] = fmaxf(acc[mi][ni][0], 0.f);
                op[HW] = fmaxf(acc[mi][ni][1], 0.f);
                op[8] = fmaxf(acc[mi][ni][2], 0.f);
                op[HW + 8] = fmaxf(acc[mi][ni][3], 0.f);
            }
        }
    }
}

// ---------------------------------------------------------------------------
extern "C" void kernel_launch(void* const* d_in, const int* in_sizes, int n_in,
                              void* d_out, int out_size) {
    const float* x = (const float*)d_in[0];        // [2,256,128,128]
    const float* w_off = (const float*)d_in[1];    // [72,256,1,1]
    const float* b_off = (const float*)d_in[2];    // [72]
    const float* w_def = (const float*)d_in[3];    // [256,256,3,3]
    float* out = (float*)d_out;

    const int OFF_SMEM = OFFC * Cc * sizeof(float);   // 73728
    const int DEF_SMEM = 2 * WB + 128 * KC * 4;       // 81920

    cudaFuncSetAttribute(k_offset, cudaFuncAttributeMaxDynamicSharedMemorySize, OFF_SMEM);
    cudaFuncSetAttribute(k_deform, cudaFuncAttributeMaxDynamicSharedMemorySize, DEF_SMEM);

    k_transpose_w<<<(Oo * Cc * 9 + 255) / 256, 256>>>(w_def);
    k_offset<<<(Bb * HW) / 128, 128, OFF_SMEM>>>(x, w_off, b_off);
    k_deform<<<Bb * Hh, 512, DEF_SMEM>>>(x, out);
}

// round 6
// speedup vs baseline: 1.5702x; 1.3111x over previous
#include <cuda_runtime.h>
#include <cuda_fp16.h>
#include <cstdint>

// Problem constants
#define Bb 2
#define Cc 256
#define Hh 128
#define Ww 128
#define Oo 256
#define HW 16384            // H*W
#define DG 4
#define OFFC 72             // DG*9*2 offset channels
#define NCH 72              // chunks: (g*2+chalf)*9 + tap, K=32 each
#define WROW 40             // fp16 per W smem row (80B: 32 data + 8 pad)
#define WCHUNK (256 * WROW) // fp16 elems per W chunk (20480B)
#define WB2 20480           // W chunk bytes
#define SB2 10240           // S buffer bytes: 128 rows x 80B

// Scratch (device globals: allocation-free rule)
__device__ float g_off[Bb * OFFC * HW];        // offset field [b][72][h][w]
__device__ __half g_wt[NCH * WCHUNK];          // fp16 weights, padded rows, per chunk

// ---------------------------------------------------------------------------
// helpers
// ---------------------------------------------------------------------------
__device__ __forceinline__ uint32_t smem_u32(const void* p) {
    uint32_t a;
    asm("{ .reg .u64 t; cvta.to.shared.u64 t, %1; cvt.u32.u64 %0, t; }" : "=r"(a) : "l"(p));
    return a;
}
__device__ __forceinline__ void ldsm4(uint32_t* r, uint32_t addr) {
    asm volatile("ldmatrix.sync.aligned.m8n8.x4.shared.b16 {%0,%1,%2,%3}, [%4];"
                 : "=r"(r[0]), "=r"(r[1]), "=r"(r[2]), "=r"(r[3]) : "r"(addr));
}
__device__ __forceinline__ void mma_f16(float* c, const uint32_t* a, const uint32_t* b) {
    asm volatile(
        "mma.sync.aligned.m16n8k16.row.col.f32.f16.f16.f32 "
        "{%0,%1,%2,%3},{%4,%5,%6,%7},{%8,%9},{%0,%1,%2,%3};"
        : "+f"(c[0]), "+f"(c[1]), "+f"(c[2]), "+f"(c[3])
        : "r"(a[0]), "r"(a[1]), "r"(a[2]), "r"(a[3]), "r"(b[0]), "r"(b[1]));
}
__device__ __forceinline__ void sts128u(uint32_t a, uint32_t x, uint32_t y, uint32_t z, uint32_t w) {
    asm volatile("st.shared.v4.b32 [%0], {%1,%2,%3,%4};" :: "r"(a), "r"(x), "r"(y), "r"(z), "r"(w));
}
__device__ __forceinline__ void cp16(uint32_t dst, const void* src) {
    asm volatile("cp.async.cg.shared.global [%0], [%1], 16;" :: "r"(dst), "l"(src) : "memory");
}
__device__ __forceinline__ void cp_commit() {
    asm volatile("cp.async.commit_group;" ::: "memory");
}
template <int N>
__device__ __forceinline__ void cp_wait() {
    asm volatile("cp.async.wait_group %0;" :: "n"(N) : "memory");
}
// f32x2 packed-FMA helpers (K1)
__device__ __forceinline__ unsigned long long pack2(float v) {
    unsigned long long r;
    asm("mov.b64 %0, {%1, %1};" : "=l"(r) : "f"(v));
    return r;
}
__device__ __forceinline__ void fma2(unsigned long long& d, unsigned long long a,
                                     unsigned long long b) {
    asm("fma.rn.f32x2 %0, %1, %2, %0;" : "+l"(d) : "l"(a), "l"(b));
}
__device__ __forceinline__ void unpack2(unsigned long long r, float& lo, float& hi) {
    asm("mov.b64 {%0, %1}, %2;" : "=f"(lo), "=f"(hi) : "l"(r));
}

// ---------------------------------------------------------------------------
// K0: transpose + fp16-round deform weights into padded per-chunk tiles.
// [O][C][3][3] -> g_wt[cid=(g*2+chalf)*9+tap][o*40 + cc]   (cc in 0..31)
// ---------------------------------------------------------------------------
__global__ void k_transpose_w(const float* __restrict__ w) {
    int idx = blockIdx.x * blockDim.x + threadIdx.x;
    if (idx >= Oo * Cc * 9) return;
    int o = idx / (Cc * 9);
    int r = idx % (Cc * 9);
    int c = r / 9;
    int tap = r % 9;
    int g = c >> 6;
    int chalf = (c >> 5) & 1;
    int cc = c & 31;
    int cid = (g * 2 + chalf) * 9 + tap;
    g_wt[(size_t)cid * WCHUNK + o * WROW + cc] = __float2half_rn(w[idx]);
}

// ---------------------------------------------------------------------------
// K1: offset field = 1x1 conv (72x256 matvec per pixel) + bias. f32x2 FMAs.
// 256 threads x 128 blocks = 1 wave.
// ---------------------------------------------------------------------------
__global__ __launch_bounds__(256) void k_offset(const float* __restrict__ x,
                                                const float* __restrict__ w_off,
                                                const float* __restrict__ b_off) {
    extern __shared__ float ws[];  // [256][72], c-major
    for (int i = threadIdx.x; i < OFFC * Cc; i += blockDim.x) {
        int o = i / Cc, c = i % Cc;
        ws[c * OFFC + o] = w_off[i];
    }
    __syncthreads();

    int pix = blockIdx.x * 256 + threadIdx.x;   // 0..32767
    int b = pix >> 14;
    int hw = pix & (HW - 1);
    const float* xp = x + (size_t)b * Cc * HW + hw;

    unsigned long long acc2[36];
#pragma unroll
    for (int i = 0; i < 36; i++) acc2[i] = ((const unsigned long long*)b_off)[i];

    for (int c = 0; c < Cc; c++) {
        float v = __ldg(&xp[(size_t)c * HW]);
        unsigned long long vv = pack2(v);
        const float4* wrow = (const float4*)&ws[c * OFFC];
#pragma unroll
        for (int i = 0; i < 18; i++) {
            float4 w4 = wrow[i];
            unsigned long long w01, w23;
            asm("mov.b64 %0, {%1, %2};" : "=l"(w01) : "f"(w4.x), "f"(w4.y));
            asm("mov.b64 %0, {%1, %2};" : "=l"(w23) : "f"(w4.z), "f"(w4.w));
            fma2(acc2[i * 2], vv, w01);
            fma2(acc2[i * 2 + 1], vv, w23);
        }
    }
    float* op = g_off + (size_t)b * OFFC * HW + hw;
#pragma unroll
    for (int i = 0; i < 36; i++) {
        float lo, hi;
        unpack2(acc2[i], lo, hi);
        op[(2 * i) * HW] = lo;
        op[(2 * i + 1) * HW] = hi;
    }
}

// ---------------------------------------------------------------------------
// K2: fused deformable conv + ReLU, fp16 mma.sync m16n8k16, fp32 accum.
// CTA = (b, row h): 128 pixels x 256 outputs. 72 K-chunks of 32c, tap-inner
// order (gather window L1-resident across 9 taps).
// Software pipeline, ONE barrier per chunk:
//   cp_wait(W(t)) -> sts S[t&1] -> sync -> cp.async W(t+1) -> sample(t+1) -> gemm(t)
// 16 warps = 4(p-quarter, 32p) x 4(o-quarter, 64o). smem 61.4KB, padded 80B rows.
// ---------------------------------------------------------------------------
__global__ __launch_bounds__(512, 1) void k_deform(const float* __restrict__ x,
                                                   float* __restrict__ out) {
    extern __shared__ float dsm[];
    const uint32_t base = smem_u32(dsm);
    const uint32_t sWb[2] = {base, base + WB2};
    const uint32_t sSb[2] = {base + 2 * WB2, base + 2 * WB2 + SB2};

    const int bx = blockIdx.x;
    const int h = bx & 127;
    const int b = bx >> 7;
    const int tid = threadIdx.x;
    const int lid = tid & 31;
    const int wid = tid >> 5;
    const int wp = wid >> 2;       // p-quarter (32p)
    const int wo = wid & 3;        // o-quarter (64o)

    // ldmatrix lane addressing
    const uint32_t a_row16 = lid & 15;
    const uint32_t a_csel = lid >> 4;                       // 16B unit within k16
    const uint32_t b_row8 = (lid & 7) + ((lid >> 4) & 1) * 8;
    const uint32_t b_csel = (lid >> 3) & 1;

    float acc[2][8][4];
#pragma unroll
    for (int i = 0; i < 2; i++)
#pragma unroll
        for (int j = 0; j < 8; j++)
#pragma unroll
            for (int k = 0; k < 4; k++) acc[i][j][k] = 0.f;

    const int sp = tid & 127;      // this thread's pixel
    const int cq = tid >> 7;       // 0..3: which 8 channels of the 32-chunk

    // --- sampler for chunk cid -> 4 packed half2 (8 channels) ---
    auto sample = [&](int cid, uint32_t* v4) {
        const int gc = cid / 9;          // g*2+chalf
        const int tap = cid - gc * 9;
        const int g = gc >> 1;
        const float* offp = g_off + ((size_t)(b * OFFC + g * 18 + tap * 2)) * HW + h * Ww + sp;
        float dy = __ldg(offp);
        float dx = __ldg(offp + HW);
        float ys = (float)(h - 1 + tap / 3) + dy;
        float xs = (float)(sp - 1 + tap % 3) + dx;
        float y0f = floorf(ys), x0f = floorf(xs);
        float ly = ys - y0f, lx = xs - x0f;
        int y0 = (int)y0f, x0i = (int)x0f;
        float wt[4];
        const float* qp[4];
        const float* xb = x + ((size_t)(b * Cc + gc * 32 + cq * 8)) * HW;
#pragma unroll
        for (int j = 0; j < 4; ++j) {
            int yj = y0 + (j >> 1);
            int xj = x0i + (j & 1);
            float wj = ((j >> 1) ? ly : 1.f - ly) * ((j & 1) ? lx : 1.f - lx);
            bool vv = (yj >= 0) && (yj < Hh) && (xj >= 0) && (xj < Ww);
            int yc = min(max(yj, 0), Hh - 1);
            int xc = min(max(xj, 0), Ww - 1);
            wt[j] = vv ? wj : 0.f;
            qp[j] = xb + (yc * Ww + xc);
        }
#pragma unroll
        for (int jj = 0; jj < 4; ++jj) {
            float s0, s1;
#pragma unroll
            for (int e = 0; e < 2; ++e) {
                int c = jj * 2 + e;
                float s = wt[0] * __ldg(qp[0] + (size_t)c * HW) +
                          wt[1] * __ldg(qp[1] + (size_t)c * HW) +
                          wt[2] * __ldg(qp[2] + (size_t)c * HW) +
                          wt[3] * __ldg(qp[3] + (size_t)c * HW);
                if (e == 0) s0 = s; else s1 = s;
            }
            __half2 hh = __floats2half2_rn(s0, s1);
            v4[jj] = *(uint32_t*)&hh;
        }
    };

    // --- prologue: prefetch W(0), sample(0) ---
    {
        const char* wsrc = (const char*)(g_wt);
        for (int i = tid; i < WB2 / 16; i += 512)
            cp16(sWb[0] + (uint32_t)i * 16u, wsrc + i * 16);
        cp_commit();
    }
    uint32_t v4[4];
    sample(0, v4);

    const uint32_t s_addr_base = (uint32_t)(sp * 80 + cq * 16);

    for (int t = 0; t < NCH; ++t) {
        const int buf = t & 1;

        cp_wait<0>();   // this thread's W(t) copies done
        sts128u(sSb[buf] + s_addr_base, v4[0], v4[1], v4[2], v4[3]);
        __syncthreads();  // all sts + all threads' W(t) copies complete

        if (t + 1 < NCH) {
            const char* wsrc = (const char*)(g_wt + (size_t)(t + 1) * WCHUNK);
            const uint32_t wdst = sWb[(t + 1) & 1];
            for (int i = tid; i < WB2 / 16; i += 512)
                cp16(wdst + (uint32_t)i * 16u, wsrc + i * 16);
            cp_commit();
            sample(t + 1, v4);   // LDG latency hides under gemm(t)
        }

        // --- GEMM: acc[32p x 64o per warp] += S * W^T over 32 c ---
#pragma unroll
        for (int ks = 0; ks < 2; ++ks) {
            uint32_t afr[2][4];
#pragma unroll
            for (int mi = 0; mi < 2; ++mi) {
                uint32_t row = (uint32_t)(wp * 32 + mi * 16) + a_row16;
                ldsm4(afr[mi], sSb[buf] + row * 80u + ((uint32_t)(ks * 2) + a_csel) * 16u);
            }
            uint32_t bfr[4][4];
#pragma unroll
            for (int pi = 0; pi < 4; ++pi) {
                uint32_t row = (uint32_t)(wo * 64 + pi * 16) + b_row8;
                ldsm4(bfr[pi], sWb[buf] + row * 80u + ((uint32_t)(ks * 2) + b_csel) * 16u);
            }
#pragma unroll
            for (int mi = 0; mi < 2; ++mi)
#pragma unroll
                for (int ni = 0; ni < 8; ++ni)
                    mma_f16(acc[mi][ni], afr[mi], &bfr[ni >> 1][(ni & 1) * 2]);
        }
    }

    // --- epilogue: ReLU + store ---
    {
        const int gq = lid >> 2;   // 0..7 (p within 16-tile)
        const int tq = lid & 3;    // 0..3 (o pairs)
#pragma unroll
        for (int mi = 0; mi < 2; ++mi) {
#pragma unroll
            for (int ni = 0; ni < 8; ++ni) {
                int o = wo * 64 + ni * 8 + 2 * tq;
                int p = wp * 32 + mi * 16 + gq;
                float* op = out + ((size_t)(b * Oo + o)) * HW + h * Ww + p;
                op[0] = fmaxf(acc[mi][ni][0], 0.f);
                op[HW] = fmaxf(acc[mi][ni][1], 0.f);
                op[8] = fmaxf(acc[mi][ni][2], 0.f);
                op[HW + 8] = fmaxf(acc[mi][ni][3], 0.f);
            }
        }
    }
}

// ---------------------------------------------------------------------------
extern "C" void kernel_launch(void* const* d_in, const int* in_sizes, int n_in,
                              void* d_out, int out_size) {
    const float* x = (const float*)d_in[0];        // [2,256,128,128]
    const float* w_off = (const float*)d_in[1];    // [72,256,1,1]
    const float* b_off = (const float*)d_in[2];    // [72]
    const float* w_def = (const float*)d_in[3];    // [256,256,3,3]
    float* out = (float*)d_out;

    const int OFF_SMEM = OFFC * Cc * sizeof(float);   // 73728
    const int DEF_SMEM = 2 * WB2 + 2 * SB2;           // 61440

    cudaFuncSetAttribute(k_offset, cudaFuncAttributeMaxDynamicSharedMemorySize, OFF_SMEM);
    cudaFuncSetAttribute(k_deform, cudaFuncAttributeMaxDynamicSharedMemorySize, DEF_SMEM);

    k_transpose_w<<<(Oo * Cc * 9 + 255) / 256, 256>>>(w_def);
    k_offset<<<(Bb * HW) / 256, 256, OFF_SMEM>>>(x, w_off, b_off);
    k_deform<<<Bb * Hh, 512, DEF_SMEM>>>(x, out);
}